// round 2
// baseline (speedup 1.0000x reference)
#include <cuda_runtime.h>

// Problem shape (fixed by the dataset)
#define BB 16
#define NN 512
#define FF 256
#define M_TOT (BB * NN)   // 8192

// Scratch for h = x @ W^T + b  (8 MB; fits in L2)
__device__ float g_h[BB * NN * FF];

// ---------------------------------------------------------------------------
// Kernel A: h[m, n] = sum_k x[m, k] * W[n, k] + bias[n]
// M=8192, N=256, K=256, fp32 SGEMM, BM=128 BN=64 BK=16, 256 threads, 8x4 micro
// ---------------------------------------------------------------------------
#define BM 128
#define BN 64
#define BK 16

__global__ __launch_bounds__(256) void gemm_h_kernel(
    const float* __restrict__ X,
    const float* __restrict__ W,
    const float* __restrict__ bias)
{
    __shared__ float As[BK][BM];   // k-major transposed
    __shared__ float Bs[BK][BN];

    const int t  = threadIdx.x;
    const int tx = t & 15;          // 0..15  -> 4 cols each
    const int ty = t >> 4;          // 0..15  -> 8 rows each
    const int m0 = blockIdx.y * BM;
    const int n0 = blockIdx.x * BN;

    const float4* X4 = reinterpret_cast<const float4*>(X);
    const float4* W4 = reinterpret_cast<const float4*>(W);

    float acc[8][4];
#pragma unroll
    for (int i = 0; i < 8; i++)
#pragma unroll
        for (int j = 0; j < 4; j++) acc[i][j] = 0.0f;

    for (int kt = 0; kt < FF; kt += BK) {
        // Load A tile: 128x16 floats = 512 float4, 2 per thread
#pragma unroll
        for (int p = 0; p < 2; p++) {
            int e   = t + p * 256;          // 0..511
            int row = e >> 2;               // 0..127
            int kg  = (e & 3) * 4;          // 0,4,8,12
            float4 v = X4[(size_t)(m0 + row) * (FF / 4) + (kt >> 2) + (e & 3)];
            As[kg + 0][row] = v.x;
            As[kg + 1][row] = v.y;
            As[kg + 2][row] = v.z;
            As[kg + 3][row] = v.w;
        }
        // Load B tile: 64x16 floats = 256 float4, 1 per thread
        {
            int e   = t;
            int row = e >> 2;               // 0..63
            int kg  = (e & 3) * 4;
            float4 v = W4[(size_t)(n0 + row) * (FF / 4) + (kt >> 2) + (e & 3)];
            Bs[kg + 0][row] = v.x;
            Bs[kg + 1][row] = v.y;
            Bs[kg + 2][row] = v.z;
            Bs[kg + 3][row] = v.w;
        }
        __syncthreads();

#pragma unroll
        for (int k = 0; k < BK; k++) {
            float4 a0 = *reinterpret_cast<const float4*>(&As[k][ty * 8]);
            float4 a1 = *reinterpret_cast<const float4*>(&As[k][ty * 8 + 4]);
            float4 bv = *reinterpret_cast<const float4*>(&Bs[k][tx * 4]);
            float a[8] = {a0.x, a0.y, a0.z, a0.w, a1.x, a1.y, a1.z, a1.w};
            float b[4] = {bv.x, bv.y, bv.z, bv.w};
#pragma unroll
            for (int i = 0; i < 8; i++)
#pragma unroll
                for (int j = 0; j < 4; j++)
                    acc[i][j] += a[i] * b[j];
        }
        __syncthreads();
    }

    // Epilogue: add bias, store h
    float4 b4 = *reinterpret_cast<const float4*>(&bias[n0 + tx * 4]);
    float4* H4 = reinterpret_cast<float4*>(g_h);
#pragma unroll
    for (int i = 0; i < 8; i++) {
        float4 r;
        r.x = acc[i][0] + b4.x;
        r.y = acc[i][1] + b4.y;
        r.z = acc[i][2] + b4.z;
        r.w = acc[i][3] + b4.w;
        H4[(size_t)(m0 + ty * 8 + i) * (FF / 4) + (n0 >> 2) + tx] = r;
    }
}

// ---------------------------------------------------------------------------
// Kernel B: fused sparse aggregation + leaky_relu + gate + blend
//   h_prime = leaky_relu(adj @ h, 0.2)
//   coeff   = sigmoid([x, h_prime] . gate_w + gate_b)
//   out     = coeff * x + (1 - coeff) * h_prime
// One CTA = (batch b, 64 consecutive i rows). h rows staged through smem in
// 64-row tiles; adj zeros skipped via warp-uniform ballot.
// ---------------------------------------------------------------------------
#define ICHUNK 64
#define JTILE  64

__global__ __launch_bounds__(256) void aggregate_kernel(
    const float* __restrict__ X,
    const float* __restrict__ ADJ,
    const float* __restrict__ GW,
    const float* __restrict__ GB,
    float* __restrict__ OUT)
{
    extern __shared__ float htile[];   // [JTILE][FF] = 64 KB

    const int b    = blockIdx.y;
    const int i0   = blockIdx.x * ICHUNK;
    const int t    = threadIdx.x;
    const int w    = t >> 5;           // warp 0..7, each owns 8 i rows
    const int lane = t & 31;           // lane owns features lane*8 .. lane*8+7

    const float* hb = g_h + (size_t)b * NN * FF;

    float acc[8][8];
#pragma unroll
    for (int ii = 0; ii < 8; ii++)
#pragma unroll
        for (int c = 0; c < 8; c++) acc[ii][c] = 0.0f;

    for (int jt = 0; jt < NN / JTILE; jt++) {
        // Cooperative load of h[b, jt*64 .. +63, :] into smem (4096 float4)
        const float4* src = reinterpret_cast<const float4*>(hb + (size_t)jt * JTILE * FF);
        float4* dst = reinterpret_cast<float4*>(htile);
#pragma unroll
        for (int r = 0; r < 16; r++)
            dst[t + r * 256] = src[t + r * 256];
        __syncthreads();

#pragma unroll
        for (int ii = 0; ii < 8; ii++) {
            const float* arow = ADJ + ((size_t)b * NN + i0 + w * 8 + ii) * NN + jt * JTILE;
#pragma unroll
            for (int g = 0; g < 2; g++) {
                float av = arow[g * 32 + lane];
                unsigned mask = __ballot_sync(0xffffffffu, av > 0.0f);
                while (mask) {
                    int j = g * 32 + (__ffs(mask) - 1);
                    mask &= mask - 1;
                    const float* hr = htile + j * FF + lane * 8;
                    float4 h0 = *reinterpret_cast<const float4*>(hr);
                    float4 h1 = *reinterpret_cast<const float4*>(hr + 4);
                    acc[ii][0] += h0.x; acc[ii][1] += h0.y;
                    acc[ii][2] += h0.z; acc[ii][3] += h0.w;
                    acc[ii][4] += h1.x; acc[ii][5] += h1.y;
                    acc[ii][6] += h1.z; acc[ii][7] += h1.w;
                }
            }
        }
        __syncthreads();
    }

    // Gate weights owned by this lane
    float gwx[8], gwh[8];
#pragma unroll
    for (int c = 0; c < 8; c++) {
        gwx[c] = GW[lane * 8 + c];
        gwh[c] = GW[FF + lane * 8 + c];
    }
    const float gb = GB[0];

#pragma unroll
    for (int ii = 0; ii < 8; ii++) {
        const int i = i0 + w * 8 + ii;
        const float* xr = X + ((size_t)b * NN + i) * FF + lane * 8;
        float4 x0 = *reinterpret_cast<const float4*>(xr);
        float4 x1 = *reinterpret_cast<const float4*>(xr + 4);
        float xv[8] = {x0.x, x0.y, x0.z, x0.w, x1.x, x1.y, x1.z, x1.w};

        float hp[8];
#pragma unroll
        for (int c = 0; c < 8; c++) {
            float v = acc[ii][c];
            hp[c] = (v > 0.0f) ? v : 0.2f * v;
        }

        // gate dot product: [x, h_prime] . gate_w
        float p = 0.0f;
#pragma unroll
        for (int c = 0; c < 8; c++)
            p += xv[c] * gwx[c] + hp[c] * gwh[c];
#pragma unroll
        for (int off = 16; off > 0; off >>= 1)
            p += __shfl_xor_sync(0xffffffffu, p, off);

        float gv = p + gb;
        float coeff = 1.0f / (1.0f + expf(-gv));
        float om = 1.0f - coeff;

        float4 o0, o1;
        o0.x = coeff * xv[0] + om * hp[0];
        o0.y = coeff * xv[1] + om * hp[1];
        o0.z = coeff * xv[2] + om * hp[2];
        o0.w = coeff * xv[3] + om * hp[3];
        o1.x = coeff * xv[4] + om * hp[4];
        o1.y = coeff * xv[5] + om * hp[5];
        o1.z = coeff * xv[6] + om * hp[6];
        o1.w = coeff * xv[7] + om * hp[7];

        float* orow = OUT + ((size_t)b * NN + i) * FF + lane * 8;
        *reinterpret_cast<float4*>(orow)     = o0;
        *reinterpret_cast<float4*>(orow + 4) = o1;
    }
}

// ---------------------------------------------------------------------------
extern "C" void kernel_launch(void* const* d_in, const int* in_sizes, int n_in,
                              void* d_out, int out_size)
{
    const float* x    = (const float*)d_in[0];   // [16,512,256]
    const float* adj  = (const float*)d_in[1];   // [16,512,512]
    const float* W_w  = (const float*)d_in[2];   // [256,256]
    const float* W_b  = (const float*)d_in[3];   // [256]
    // d_in[4] = A : dead code in the reference (attention is never used)
    const float* gw   = (const float*)d_in[5];   // [1,512]
    const float* gb   = (const float*)d_in[6];   // [1]
    float* out = (float*)d_out;

    dim3 gridA(FF / BN, M_TOT / BM);             // (4, 64)
    gemm_h_kernel<<<gridA, 256>>>(x, W_w, W_b);

    cudaFuncSetAttribute(aggregate_kernel,
                         cudaFuncAttributeMaxDynamicSharedMemorySize,
                         JTILE * FF * sizeof(float));
    dim3 gridB(NN / ICHUNK, BB);                 // (8, 16)
    aggregate_kernel<<<gridB, 256, JTILE * FF * sizeof(float)>>>(
        x, adj, gw, gb, out);
}